// round 16
// baseline (speedup 1.0000x reference)
#include <cuda_runtime.h>
#include <math.h>
#include <stdint.h>

#define S    8
#define H    128
#define BB   4096
#define NBLK 296     // 148 SMs x 2 CTAs, one balanced wave; ~14 batches/CTA
#define NT   256     // 8 warps

#define WS_STR 136   // Ws stride: 136%32==8 -> B-frag bank = 8*qd+gp, conflict-free
#define CS_STR 132   // Cs stride: 132%32==4 -> A-frag bank = 4*gp+qd, conflict-free

// Dynamic smem layout (floats)
#define OFF_WS   0                         // Ws [128][WS_STR]  17408 floats
#define OFF_CS   (128 * WS_STR)            // Cs [16][CS_STR]   (tf32 bits)
#define OFF_NS   (OFF_CS + 16 * CS_STR)    // ns [8][128]
#define OFF_U1   (OFF_NS + S * H)          // u1s[128]
#define OFF_U2   (OFF_U1 + H)              // u2s[128]
#define SMEM_FLOATS (OFF_U2 + H)
#define SMEM_BYTES  (SMEM_FLOATS * 4)

__device__ __forceinline__ void cp_async16(uint32_t saddr, const void* gptr) {
    asm volatile("cp.async.cg.shared.global [%0], [%1], 16;"
                 :: "r"(saddr), "l"(gptr));
}
__device__ __forceinline__ uint32_t tf32(float f) {
    uint32_t r;
    asm("cvt.rna.tf32.f32 %0, %1;" : "=r"(r) : "f"(f));
    return r;
}
// m16n8k8 tf32, row.col (layout verified by R15 pass):
__device__ __forceinline__ void mma_tf32_k8(float* d,
                                            uint32_t a0, uint32_t a1,
                                            uint32_t a2, uint32_t a3,
                                            uint32_t b0, uint32_t b1) {
    asm volatile(
        "mma.sync.aligned.m16n8k8.row.col.f32.tf32.tf32.f32 "
        "{%0,%1,%2,%3}, {%4,%5,%6,%7}, {%8,%9}, {%0,%1,%2,%3};"
        : "+f"(d[0]), "+f"(d[1]), "+f"(d[2]), "+f"(d[3])
        : "r"(a0), "r"(a1), "r"(a2), "r"(a3), "r"(b0), "r"(b1));
}

__global__ __launch_bounds__(NT, 2)
void fused_kernel(const float* __restrict__ memory,
                  const float* __restrict__ o_emb_w,
                  const float* __restrict__ o_emb_r,
                  const float* __restrict__ attn_W,
                  const float* __restrict__ sim_w,
                  const float* __restrict__ sim_b,
                  const float* __restrict__ forget_w,
                  const int*   __restrict__ o_rg_p,
                  const int*   __restrict__ d_rg,
                  float*       __restrict__ out)
{
    extern __shared__ float sm[];
    float*    Ws  = sm + OFF_WS;                 // [128][WS_STR] fp32
    uint32_t* CsB = (uint32_t*)(sm + OFF_CS);    // [16][CS_STR]  tf32 bits
    float*    ns  = sm + OFF_NS;
    float*    u1s = sm + OFF_U1;
    float*    u2s = sm + OFF_U2;

    const int tid  = threadIdx.x;
    const int warp = tid >> 5;       // 0..7
    const int lane = tid & 31;
    const unsigned F = 0xffffffffu;

    // Balanced batch chunking: start = bid*4096/296 = bid*512/37
    const int start = (blockIdx.x * 512) / 37;
    const int nb    = ((blockIdx.x + 1) * 512) / 37 - start;   // 13 or 14

    // ============ PHASE A ============
    // 0) Index loads FIRST — longest dependency chains start immediately.
    const int orr = o_rg_p[0];
    const int bA = start + warp;           // always valid (nb >= 13 > 8)
    const int bB = start + warp + 8;
    const bool hasB = (warp + 8) < nb;
    const int rA = d_rg[bA];
    const int rB = hasB ? d_rg[bB] : rA;

    // 1) W -> Ws via cp.async (streams behind everything; awaited pre-GEMM)
    {
        uint32_t ws_addr = (uint32_t)__cvta_generic_to_shared(Ws);
#pragma unroll
        for (int i = 0; i < 16; i++) {
            const int g     = tid + i * NT;      // 0..4095
            const int row   = g >> 5;            // 0..127
            const int chunk = g & 31;            // 0..31 (4 floats each)
            cp_async16(ws_addr + (uint32_t)(row * WS_STR + chunk * 4) * 4u,
                       attn_W + row * H + chunk * 4);
        }
        asm volatile("cp.async.commit_group;");
    }

    // 2) o_emb_r rows (independent of rA/rB — issue while d_rg is in flight)
    float4 oA = ((const float4*)(o_emb_r + (size_t)bA * H))[lane];
    float4 oB = hasB ? ((const float4*)(o_emb_r + (size_t)bB * H))[lane]
                     : make_float4(0.f, 0.f, 0.f, 0.f);

    // 3) BOTH gathers in phase A — DRAM latency hides under gate + u1/u2
    float4 kmA[S], kmB[S];
    {
        const float4* sA = (const float4*)(memory + (size_t)rA * (S * H));
#pragma unroll
        for (int s = 0; s < S; s++) kmA[s] = sA[s * 32 + lane];
    }
    if (hasB) {
        const float4* sB = (const float4*)(memory + (size_t)rB * (S * H));
#pragma unroll
        for (int s = 0; s < S; s++) kmB[s] = sB[s * 32 + lane];
    } else {
#pragma unroll
        for (int s = 0; s < S; s++) kmB[s] = make_float4(0.f, 0.f, 0.f, 0.f);
    }

    // 4) gate + new_slot (warp w = slot w)
    {
        const float4* sel4 = (const float4*)(memory + (size_t)orr * (S * H) + warp * H);
        float4 v  = sel4[lane];
        float4 oe = ((const float4*)o_emb_w)[lane];
        float4 f1 = ((const float4*)forget_w)[lane];
        float4 f2 = ((const float4*)(forget_w + H))[lane];
        float d = oe.x*f1.x + oe.y*f1.y + oe.z*f1.z + oe.w*f1.w
                + v.x*f2.x  + v.y*f2.y  + v.z*f2.z  + v.w*f2.w;
#pragma unroll
        for (int off = 16; off > 0; off >>= 1)
            d += __shfl_xor_sync(F, d, off);
        float g = 1.f / (1.f + __expf(-d));
        float4 nv;
        nv.x = v.x + (oe.x - v.x) * g;
        nv.y = v.y + (oe.y - v.y) * g;
        nv.z = v.z + (oe.z - v.z) * g;
        nv.w = v.w + (oe.w - v.w) * g;
        ((float4*)ns)[warp * 32 + lane] = nv;
    }

    // 5) u1 = W @ sim_w[:H], u2 = W @ sim_w[H:] — from GLOBAL attn_W (L2-hot)
    {
        const float4 sw1 = ((const float4*)sim_w)[lane];
        const float4 sw2 = ((const float4*)sim_w)[32 + lane];
#pragma unroll
        for (int it = 0; it < 8; it++) {
            const int rowA2 = warp * 16 + it * 2;
            float4 wa = ((const float4*)(attn_W + (size_t)rowA2 * H))[lane];
            float4 wb = ((const float4*)(attn_W + (size_t)(rowA2 + 1) * H))[lane];
            float v0 = wa.x*sw1.x + wa.y*sw1.y + wa.z*sw1.z + wa.w*sw1.w;
            float v1 = wa.x*sw2.x + wa.y*sw2.y + wa.z*sw2.z + wa.w*sw2.w;
            float v2 = wb.x*sw1.x + wb.y*sw1.y + wb.z*sw1.z + wb.w*sw1.w;
            float v3 = wb.x*sw2.x + wb.y*sw2.y + wb.z*sw2.z + wb.w*sw2.w;
            const bool h16 = lane & 16;
            float k0 = h16 ? v2 : v0, k1 = h16 ? v3 : v1;
            float s0 = h16 ? v0 : v2, s1 = h16 ? v1 : v3;
            k0 += __shfl_xor_sync(F, s0, 16);
            k1 += __shfl_xor_sync(F, s1, 16);
            const bool h8 = lane & 8;
            float m = h8 ? k1 : k0;
            float t = h8 ? k0 : k1;
            m += __shfl_xor_sync(F, t, 8);
            m += __shfl_xor_sync(F, m, 4);
            m += __shfl_xor_sync(F, m, 2);
            m += __shfl_xor_sync(F, m, 1);
            if ((lane & 7) == 0) {
                const int cls = lane >> 3;
                float* dst = (cls & 1) ? u2s : u1s;
                dst[rowA2 + ((cls & 2) >> 1)] = m;
            }
        }
    }
    __syncthreads();   // ns, u1s, u2s ready (Ws fill still in flight)

    // ============ ATTEND: A and B interleaved (2-way ILP on every fold) =====
    {
        const float4 u1v = ((const float4*)u1s)[lane];
        const float4 u2v = ((const float4*)u2s)[lane];
        const float  c   = sim_b[0];
        const float4* ns4 = (const float4*)ns;
        if (rA == orr) {
#pragma unroll
            for (int s = 0; s < S; s++) kmA[s] = ns4[s * 32 + lane];
        }
        if (hasB && rB == orr) {
#pragma unroll
            for (int s = 0; s < S; s++) kmB[s] = ns4[s * 32 + lane];
        }

        float aA = oA.x*u1v.x + oA.y*u1v.y + oA.z*u1v.z + oA.w*u1v.w;
        float aB = oB.x*u1v.x + oB.y*u1v.y + oB.z*u1v.z + oB.w*u1v.w;
        float pA[S], pB[S];
#pragma unroll
        for (int s = 0; s < S; s++) {
            pA[s] = kmA[s].x*u2v.x + kmA[s].y*u2v.y + kmA[s].z*u2v.z + kmA[s].w*u2v.w + aA;
            pB[s] = kmB[s].x*u2v.x + kmB[s].y*u2v.y + kmB[s].z*u2v.z + kmB[s].w*u2v.w + aB;
        }

        // fold 16: keep 4, send 4 (A and B interleaved)
        const bool h16 = lane & 16;
        float kA0 = h16 ? pA[4] : pA[0], kA1 = h16 ? pA[5] : pA[1];
        float kA2 = h16 ? pA[6] : pA[2], kA3 = h16 ? pA[7] : pA[3];
        float sA0 = h16 ? pA[0] : pA[4], sA1 = h16 ? pA[1] : pA[5];
        float sA2 = h16 ? pA[2] : pA[6], sA3 = h16 ? pA[3] : pA[7];
        float kB0 = h16 ? pB[4] : pB[0], kB1 = h16 ? pB[5] : pB[1];
        float kB2 = h16 ? pB[6] : pB[2], kB3 = h16 ? pB[7] : pB[3];
        float sB0 = h16 ? pB[0] : pB[4], sB1 = h16 ? pB[1] : pB[5];
        float sB2 = h16 ? pB[2] : pB[6], sB3 = h16 ? pB[3] : pB[7];
        kA0 += __shfl_xor_sync(F, sA0, 16);
        kB0 += __shfl_xor_sync(F, sB0, 16);
        kA1 += __shfl_xor_sync(F, sA1, 16);
        kB1 += __shfl_xor_sync(F, sB1, 16);
        kA2 += __shfl_xor_sync(F, sA2, 16);
        kB2 += __shfl_xor_sync(F, sB2, 16);
        kA3 += __shfl_xor_sync(F, sA3, 16);
        kB3 += __shfl_xor_sync(F, sB3, 16);
        // fold 8
        const bool h8 = lane & 8;
        float mA0 = h8 ? kA2 : kA0, mA1 = h8 ? kA3 : kA1;
        float tA0 = h8 ? kA0 : kA2, tA1 = h8 ? kA1 : kA3;
        float mB0 = h8 ? kB2 : kB0, mB1 = h8 ? kB3 : kB1;
        float tB0 = h8 ? kB0 : kB2, tB1 = h8 ? kB1 : kB3;
        mA0 += __shfl_xor_sync(F, tA0, 8);
        mB0 += __shfl_xor_sync(F, tB0, 8);
        mA1 += __shfl_xor_sync(F, tA1, 8);
        mB1 += __shfl_xor_sync(F, tB1, 8);
        // fold 4
        const bool h4 = lane & 4;
        float qA = h4 ? mA1 : mA0, uA = h4 ? mA0 : mA1;
        float qB = h4 ? mB1 : mB0, uB = h4 ? mB0 : mB1;
        qA += __shfl_xor_sync(F, uA, 4);
        qB += __shfl_xor_sync(F, uB, 4);
        qA += __shfl_xor_sync(F, qA, 2);
        qB += __shfl_xor_sync(F, qB, 2);
        qA += __shfl_xor_sync(F, qA, 1);
        qB += __shfl_xor_sync(F, qB, 1);
        // lane class (lane>>2)&7 holds logit for slot=class

        float LA = qA + c;  LA = LA > 0.f ? LA : 0.f;
        float LB = qB + c;  LB = LB > 0.f ? LB : 0.f;
        float mxA = LA, mxB = LB;
        mxA = fmaxf(mxA, __shfl_xor_sync(F, mxA, 4));
        mxB = fmaxf(mxB, __shfl_xor_sync(F, mxB, 4));
        mxA = fmaxf(mxA, __shfl_xor_sync(F, mxA, 8));
        mxB = fmaxf(mxB, __shfl_xor_sync(F, mxB, 8));
        mxA = fmaxf(mxA, __shfl_xor_sync(F, mxA, 16));
        mxB = fmaxf(mxB, __shfl_xor_sync(F, mxB, 16));
        float eA = __expf(LA - mxA);
        float eB = __expf(LB - mxB);
        float suA = eA, suB = eB;
        suA += __shfl_xor_sync(F, suA, 4);
        suB += __shfl_xor_sync(F, suB, 4);
        suA += __shfl_xor_sync(F, suA, 8);
        suB += __shfl_xor_sync(F, suB, 8);
        suA += __shfl_xor_sync(F, suA, 16);
        suB += __shfl_xor_sync(F, suB, 16);
        float scAme = eA / suA;
        float scBme = eB / suB;

        float4 cA = make_float4(0.f, 0.f, 0.f, 0.f);
        float4 cB = make_float4(0.f, 0.f, 0.f, 0.f);
#pragma unroll
        for (int s = 0; s < S; s++) {
            float scA = __shfl_sync(F, scAme, s << 2);
            float scB = __shfl_sync(F, scBme, s << 2);
            cA.x += scA * kmA[s].x;  cA.y += scA * kmA[s].y;
            cA.z += scA * kmA[s].z;  cA.w += scA * kmA[s].w;
            cB.x += scB * kmB[s].x;  cB.y += scB * kmB[s].y;
            cB.z += scB * kmB[s].z;  cB.w += scB * kmB[s].w;
        }
        ((uint4*)(CsB + warp * CS_STR))[lane] =
            make_uint4(tf32(cA.x), tf32(cA.y), tf32(cA.z), tf32(cA.w));
        ((uint4*)(CsB + (warp + 8) * CS_STR))[lane] =
            make_uint4(tf32(cB.x), tf32(cB.y), tf32(cB.z), tf32(cB.w));
    }

    // Wait for the W fill — it streamed under gate/u/gathers/attend.
    asm volatile("cp.async.wait_group 0;" ::: "memory");
    __syncthreads();   // Cs + Ws both visible

    // ============ GEMM on tensor pipe: out = Cs @ W, tf32 m16n8k8 ============
    {
        const int n0 = warp * 16;
        const int gp = lane >> 2;   // groupID (A/D row base, B col)
        const int qd = lane & 3;    // thread-in-group

        float d0[4] = {0.f, 0.f, 0.f, 0.f};
        float d1[4] = {0.f, 0.f, 0.f, 0.f};

        const uint32_t* arow0 = CsB + gp * CS_STR + qd;        // A row gp
        const uint32_t* arow1 = CsB + (gp + 8) * CS_STR + qd;  // A row gp+8
        const float*    bcol0 = Ws + qd * WS_STR + n0 + gp;    // B col gp
        const float*    bcol1 = Ws + qd * WS_STR + n0 + 8 + gp;

#pragma unroll
        for (int kt = 0; kt < 16; kt++) {
            const int k0 = kt * 8;
            uint32_t a0 = arow0[k0];
            uint32_t a1 = arow1[k0];
            uint32_t a2 = arow0[k0 + 4];
            uint32_t a3 = arow1[k0 + 4];
            uint32_t b0 = tf32(bcol0[k0 * WS_STR]);
            uint32_t b1 = tf32(bcol0[(k0 + 4) * WS_STR]);
            uint32_t b2 = tf32(bcol1[k0 * WS_STR]);
            uint32_t b3 = tf32(bcol1[(k0 + 4) * WS_STR]);
            mma_tf32_k8(d0, a0, a1, a2, a3, b0, b1);
            mma_tf32_k8(d1, a0, a1, a2, a3, b2, b3);
        }

        // Store: c0/c1 -> row gp (always < nb), c2/c3 -> row gp+8 (predicated)
        const int col = 2 * qd;
        {
            float* o0 = out + (size_t)(start + gp) * H + n0 + col;
            *(float2*)o0       = make_float2(d0[0], d0[1]);
            *(float2*)(o0 + 8) = make_float2(d1[0], d1[1]);
        }
        if (gp + 8 < nb) {
            float* o1 = out + (size_t)(start + gp + 8) * H + n0 + col;
            *(float2*)o1       = make_float2(d0[2], d0[3]);
            *(float2*)(o1 + 8) = make_float2(d1[2], d1[3]);
        }
    }
}

// ---------------------------------------------------------------------------
extern "C" void kernel_launch(void* const* d_in, const int* in_sizes, int n_in,
                              void* d_out, int out_size)
{
    const float* memory   = (const float*)d_in[0];
    const float* o_emb_w  = (const float*)d_in[1];
    const float* o_emb_r  = (const float*)d_in[2];
    const float* attn_W   = (const float*)d_in[3];
    const float* sim_w    = (const float*)d_in[4];
    const float* sim_b    = (const float*)d_in[5];
    const float* forget_w = (const float*)d_in[6];
    const int*   o_rg     = (const int*)d_in[7];
    const int*   d_rg     = (const int*)d_in[8];
    float* out = (float*)d_out;

    cudaFuncSetAttribute(fused_kernel,
                         cudaFuncAttributeMaxDynamicSharedMemorySize, SMEM_BYTES);
    fused_kernel<<<NBLK, NT, SMEM_BYTES>>>(memory, o_emb_w, o_emb_r, attn_W,
                                           sim_w, sim_b, forget_w, o_rg, d_rg, out);
}

// round 17
// speedup vs baseline: 1.0175x; 1.0175x over previous
#include <cuda_runtime.h>
#include <math.h>
#include <stdint.h>

#define S    8
#define H    128
#define BB   4096
#define NBLK 296     // 148 SMs x 2 CTAs, one balanced wave; ~14 batches/CTA
#define NT   256     // 8 warps

#define CS_STR 132   // Cs stride: 132%32==4 -> A-frag bank = 4*gp+qd, conflict-free

// Dynamic smem layout (floats) — no W staging; ~14KB total
#define OFF_CS   0                         // Cs [16][CS_STR] (tf32 bits)
#define OFF_NS   (16 * CS_STR)             // ns [8][128]
#define OFF_U1   (OFF_NS + S * H)          // u1s[128]
#define OFF_U2   (OFF_U1 + H)              // u2s[128]
#define SMEM_FLOATS (OFF_U2 + H)
#define SMEM_BYTES  (SMEM_FLOATS * 4)

__device__ __forceinline__ uint32_t tf32(float f) {
    uint32_t r;
    asm("cvt.rna.tf32.f32 %0, %1;" : "=r"(r) : "f"(f));
    return r;
}
// m16n8k8 tf32, row.col (layout verified by R15 pass):
__device__ __forceinline__ void mma_tf32_k8(float* d,
                                            uint32_t a0, uint32_t a1,
                                            uint32_t a2, uint32_t a3,
                                            uint32_t b0, uint32_t b1) {
    asm volatile(
        "mma.sync.aligned.m16n8k8.row.col.f32.tf32.tf32.f32 "
        "{%0,%1,%2,%3}, {%4,%5,%6,%7}, {%8,%9}, {%0,%1,%2,%3};"
        : "+f"(d[0]), "+f"(d[1]), "+f"(d[2]), "+f"(d[3])
        : "r"(a0), "r"(a1), "r"(a2), "r"(a3), "r"(b0), "r"(b1));
}

// Attend one batch via fold-reduction; writes ctx row as TF32 BITS.
__device__ __forceinline__ void attend_fold(const float4* __restrict__ km,
                                            float4 o, float4 u1v, float4 u2v,
                                            float c, int lane,
                                            uint32_t* __restrict__ csRowBits)
{
    const unsigned F = 0xffffffffu;
    float a = o.x*u1v.x + o.y*u1v.y + o.z*u1v.z + o.w*u1v.w;
    float p[S];
#pragma unroll
    for (int s = 0; s < S; s++)
        p[s] = km[s].x*u2v.x + km[s].y*u2v.y + km[s].z*u2v.z + km[s].w*u2v.w + a;

    const bool h16 = lane & 16;
    float k0 = h16 ? p[4] : p[0], k1 = h16 ? p[5] : p[1];
    float k2 = h16 ? p[6] : p[2], k3 = h16 ? p[7] : p[3];
    float s0 = h16 ? p[0] : p[4], s1 = h16 ? p[1] : p[5];
    float s2 = h16 ? p[2] : p[6], s3 = h16 ? p[3] : p[7];
    k0 += __shfl_xor_sync(F, s0, 16);
    k1 += __shfl_xor_sync(F, s1, 16);
    k2 += __shfl_xor_sync(F, s2, 16);
    k3 += __shfl_xor_sync(F, s3, 16);
    const bool h8 = lane & 8;
    float m0 = h8 ? k2 : k0, m1 = h8 ? k3 : k1;
    float t0 = h8 ? k0 : k2, t1 = h8 ? k1 : k3;
    m0 += __shfl_xor_sync(F, t0, 8);
    m1 += __shfl_xor_sync(F, t1, 8);
    const bool h4 = lane & 4;
    float q = h4 ? m1 : m0;
    float u = h4 ? m0 : m1;
    q += __shfl_xor_sync(F, u, 4);
    q += __shfl_xor_sync(F, q, 2);
    q += __shfl_xor_sync(F, q, 1);
    // lane class (lane>>2)&7 holds logit for slot=class

    float L = q + c;
    L = L > 0.f ? L : 0.f;
    float mx = L;
    mx = fmaxf(mx, __shfl_xor_sync(F, mx, 4));
    mx = fmaxf(mx, __shfl_xor_sync(F, mx, 8));
    mx = fmaxf(mx, __shfl_xor_sync(F, mx, 16));
    float e = __expf(L - mx);
    float sum = e;
    sum += __shfl_xor_sync(F, sum, 4);
    sum += __shfl_xor_sync(F, sum, 8);
    sum += __shfl_xor_sync(F, sum, 16);
    float mysc = e / sum;

    float4 ctx = make_float4(0.f, 0.f, 0.f, 0.f);
#pragma unroll
    for (int s = 0; s < S; s++) {
        float sc = __shfl_sync(F, mysc, s << 2);
        ctx.x += sc * km[s].x;
        ctx.y += sc * km[s].y;
        ctx.z += sc * km[s].z;
        ctx.w += sc * km[s].w;
    }
    uint4 bits = make_uint4(tf32(ctx.x), tf32(ctx.y), tf32(ctx.z), tf32(ctx.w));
    ((uint4*)csRowBits)[lane] = bits;
}

__global__ __launch_bounds__(NT, 2)
void fused_kernel(const float* __restrict__ memory,
                  const float* __restrict__ o_emb_w,
                  const float* __restrict__ o_emb_r,
                  const float* __restrict__ attn_W,
                  const float* __restrict__ sim_w,
                  const float* __restrict__ sim_b,
                  const float* __restrict__ forget_w,
                  const int*   __restrict__ o_rg_p,
                  const int*   __restrict__ d_rg,
                  float*       __restrict__ out)
{
    extern __shared__ float sm[];
    uint32_t* CsB = (uint32_t*)(sm + OFF_CS);    // [16][CS_STR] tf32 bits
    float*    ns  = sm + OFF_NS;
    float*    u1s = sm + OFF_U1;
    float*    u2s = sm + OFF_U2;

    const int tid  = threadIdx.x;
    const int warp = tid >> 5;       // 0..7
    const int lane = tid & 31;
    const int orr  = o_rg_p[0];
    const unsigned F = 0xffffffffu;

    // Balanced batch chunking: start = bid*4096/296 = bid*512/37
    const int start = (blockIdx.x * 512) / 37;
    const int nb    = ((blockIdx.x + 1) * 512) / 37 - start;   // 13 or 14

    // ============ PHASE A ============
    // 1) gather A (+ o_emb_r rows) early — latency hides under prep
    const int bA = start + warp;           // always valid (nb >= 13 > 8)
    const int bB = start + warp + 8;
    const bool hasB = (warp + 8) < nb;
    const int rA = d_rg[bA];
    const int rB = hasB ? d_rg[bB] : rA;
    float4 kmA[S];
    {
        const float4* sA = (const float4*)(memory + (size_t)rA * (S * H));
#pragma unroll
        for (int s = 0; s < S; s++) kmA[s] = sA[s * 32 + lane];
    }
    float4 oA = ((const float4*)(o_emb_r + (size_t)bA * H))[lane];
    float4 oB = hasB ? ((const float4*)(o_emb_r + (size_t)bB * H))[lane]
                     : make_float4(0.f, 0.f, 0.f, 0.f);

    // 2) gate + new_slot (warp w = slot w)
    {
        const float4* sel4 = (const float4*)(memory + (size_t)orr * (S * H) + warp * H);
        float4 v  = sel4[lane];
        float4 oe = ((const float4*)o_emb_w)[lane];
        float4 f1 = ((const float4*)forget_w)[lane];
        float4 f2 = ((const float4*)(forget_w + H))[lane];
        float d = oe.x*f1.x + oe.y*f1.y + oe.z*f1.z + oe.w*f1.w
                + v.x*f2.x  + v.y*f2.y  + v.z*f2.z  + v.w*f2.w;
#pragma unroll
        for (int off = 16; off > 0; off >>= 1)
            d += __shfl_xor_sync(F, d, off);
        float g = 1.f / (1.f + __expf(-d));
        float4 nv;
        nv.x = v.x + (oe.x - v.x) * g;
        nv.y = v.y + (oe.y - v.y) * g;
        nv.z = v.z + (oe.z - v.z) * g;
        nv.w = v.w + (oe.w - v.w) * g;
        ((float4*)ns)[warp * 32 + lane] = nv;
    }

    // 3) u1 = W @ sim_w[:H], u2 = W @ sim_w[H:] — from GLOBAL attn_W (L2-hot)
    {
        const float4 sw1 = ((const float4*)sim_w)[lane];
        const float4 sw2 = ((const float4*)sim_w)[32 + lane];
#pragma unroll
        for (int it = 0; it < 8; it++) {
            const int rowA2 = warp * 16 + it * 2;
            float4 wa = ((const float4*)(attn_W + (size_t)rowA2 * H))[lane];
            float4 wb = ((const float4*)(attn_W + (size_t)(rowA2 + 1) * H))[lane];
            float v0 = wa.x*sw1.x + wa.y*sw1.y + wa.z*sw1.z + wa.w*sw1.w;
            float v1 = wa.x*sw2.x + wa.y*sw2.y + wa.z*sw2.z + wa.w*sw2.w;
            float v2 = wb.x*sw1.x + wb.y*sw1.y + wb.z*sw1.z + wb.w*sw1.w;
            float v3 = wb.x*sw2.x + wb.y*sw2.y + wb.z*sw2.z + wb.w*sw2.w;
            const bool h16 = lane & 16;
            float k0 = h16 ? v2 : v0, k1 = h16 ? v3 : v1;
            float s0 = h16 ? v0 : v2, s1 = h16 ? v1 : v3;
            k0 += __shfl_xor_sync(F, s0, 16);
            k1 += __shfl_xor_sync(F, s1, 16);
            const bool h8 = lane & 8;
            float m = h8 ? k1 : k0;
            float t = h8 ? k0 : k1;
            m += __shfl_xor_sync(F, t, 8);
            m += __shfl_xor_sync(F, m, 4);
            m += __shfl_xor_sync(F, m, 2);
            m += __shfl_xor_sync(F, m, 1);
            if ((lane & 7) == 0) {
                const int cls = lane >> 3;
                float* dst = (cls & 1) ? u2s : u1s;
                dst[rowA2 + ((cls & 2) >> 1)] = m;
            }
        }
    }
    __syncthreads();   // ns, u1s, u2s ready

    // 4) gather B now (hides under attend A)
    float4 kmB[S];
    if (hasB) {
        const float4* sB = (const float4*)(memory + (size_t)rB * (S * H));
#pragma unroll
        for (int s = 0; s < S; s++) kmB[s] = sB[s * 32 + lane];
    }

    // ============ ATTEND (ctx rows stored as tf32 bits) ============
    {
        const float4 u1v = ((const float4*)u1s)[lane];
        const float4 u2v = ((const float4*)u2s)[lane];
        const float  c   = sim_b[0];
        const float4* ns4 = (const float4*)ns;
        if (rA == orr) {
#pragma unroll
            for (int s = 0; s < S; s++) kmA[s] = ns4[s * 32 + lane];
        }
        attend_fold(kmA, oA, u1v, u2v, c, lane, CsB + warp * CS_STR);
        if (hasB) {
            if (rB == orr) {
#pragma unroll
                for (int s = 0; s < S; s++) kmB[s] = ns4[s * 32 + lane];
            }
            attend_fold(kmB, oB, u1v, u2v, c, lane, CsB + (warp + 8) * CS_STR);
        } else {
            // zero bits = tf32 zero; stale row contributes nothing
            ((uint4*)(CsB + (warp + 8) * CS_STR))[lane] = make_uint4(0u, 0u, 0u, 0u);
        }
    }
    __syncthreads();   // Cs visible to all warps

    // ============ GEMM on tensor pipe: out = Cs @ W, tf32 m16n8k8 ============
    // B operands read DIRECTLY from global attn_W (L2-hot, second touch):
    // no smem staging, no cp.async wait — GEMM starts as soon as Cs is ready.
    {
        const int n0 = warp * 16;
        const int gp = lane >> 2;   // groupID (A/D row base, B col)
        const int qd = lane & 3;    // thread-in-group

        float d0[4] = {0.f, 0.f, 0.f, 0.f};
        float d1[4] = {0.f, 0.f, 0.f, 0.f};

        const uint32_t* arow0 = CsB + gp * CS_STR + qd;        // A row gp
        const uint32_t* arow1 = CsB + (gp + 8) * CS_STR + qd;  // A row gp+8
        const float*    bcol0 = attn_W + (size_t)qd * H + n0 + gp;      // B[k][n]
        const float*    bcol1 = attn_W + (size_t)qd * H + n0 + 8 + gp;

#pragma unroll
        for (int kt = 0; kt < 16; kt++) {
            const int k0 = kt * 8;
            uint32_t a0 = arow0[k0];
            uint32_t a1 = arow1[k0];
            uint32_t a2 = arow0[k0 + 4];
            uint32_t a3 = arow1[k0 + 4];
            uint32_t b0 = tf32(bcol0[(size_t)k0 * H]);
            uint32_t b1 = tf32(bcol0[(size_t)(k0 + 4) * H]);
            uint32_t b2 = tf32(bcol1[(size_t)k0 * H]);
            uint32_t b3 = tf32(bcol1[(size_t)(k0 + 4) * H]);
            mma_tf32_k8(d0, a0, a1, a2, a3, b0, b1);
            mma_tf32_k8(d1, a0, a1, a2, a3, b2, b3);
        }

        // Store: c0/c1 -> row gp (always < nb), c2/c3 -> row gp+8 (predicated)
        const int col = 2 * qd;
        {
            float* o0 = out + (size_t)(start + gp) * H + n0 + col;
            *(float2*)o0       = make_float2(d0[0], d0[1]);
            *(float2*)(o0 + 8) = make_float2(d1[0], d1[1]);
        }
        if (gp + 8 < nb) {
            float* o1 = out + (size_t)(start + gp + 8) * H + n0 + col;
            *(float2*)o1       = make_float2(d0[2], d0[3]);
            *(float2*)(o1 + 8) = make_float2(d1[2], d1[3]);
        }
    }
}

// ---------------------------------------------------------------------------
extern "C" void kernel_launch(void* const* d_in, const int* in_sizes, int n_in,
                              void* d_out, int out_size)
{
    const float* memory   = (const float*)d_in[0];
    const float* o_emb_w  = (const float*)d_in[1];
    const float* o_emb_r  = (const float*)d_in[2];
    const float* attn_W   = (const float*)d_in[3];
    const float* sim_w    = (const float*)d_in[4];
    const float* sim_b    = (const float*)d_in[5];
    const float* forget_w = (const float*)d_in[6];
    const int*   o_rg     = (const int*)d_in[7];
    const int*   d_rg     = (const int*)d_in[8];
    float* out = (float*)d_out;

    cudaFuncSetAttribute(fused_kernel,
                         cudaFuncAttributeMaxDynamicSharedMemorySize, SMEM_BYTES);
    fused_kernel<<<NBLK, NT, SMEM_BYTES>>>(memory, o_emb_w, o_emb_r, attn_W,
                                           sim_w, sim_b, forget_w, o_rg, d_rg, out);
}